// round 4
// baseline (speedup 1.0000x reference)
#include <cuda_runtime.h>
#include <cuda_bf16.h>

// Problem constants (from reference)
#define N_NODES 50000
#define N_EDGES 800000
#define MAX_NEI 16
#define D 256

// Scratch for support = X @ W^T + b_lin (51.2 MB). Referenced DIRECTLY from
// device code — no host-side cudaGetSymbolAddress (removes a failure mode).
__device__ float g_support[(size_t)N_NODES * D];

// ---------------------------------------------------------------------------
// Kernel 1: tiled SGEMM  g_support[m,o] = sum_d X[m,d] * W[o,d] + b[o]
// BM=BN=64, BK=16, 256 threads, 4x4 micro-tile per thread.
// ---------------------------------------------------------------------------
#define BM 64
#define BN 64
#define BK 16

__global__ __launch_bounds__(256)
void gemm_bias_kernel(const float* __restrict__ X,
                      const float* __restrict__ W,
                      const float* __restrict__ b_lin,
                      int M)
{
    __shared__ float As[BK][BM + 1];   // As[k][m]
    __shared__ float Bs[BK][BN + 1];   // Bs[k][o]

    const int m0 = blockIdx.x * BM;
    const int n0 = blockIdx.y * BN;

    const int tx = threadIdx.x & 15;   // 0..15 -> N direction (4 cols each)
    const int ty = threadIdx.x >> 4;   // 0..15 -> M direction (4 rows each)

    const int lr = threadIdx.x >> 2;        // 0..63 (row within tile)
    const int lc = (threadIdx.x & 3) * 4;   // 0,4,8,12 (k offset within BK)

    float acc[4][4];
#pragma unroll
    for (int i = 0; i < 4; i++)
#pragma unroll
        for (int j = 0; j < 4; j++) acc[i][j] = 0.0f;

    for (int k0 = 0; k0 < D; k0 += BK) {
        const int gm = m0 + lr;
        float4 av = make_float4(0.f, 0.f, 0.f, 0.f);
        if (gm < M)
            av = *reinterpret_cast<const float4*>(X + (size_t)gm * D + k0 + lc);
        // W rows n0+lr always in range (output dim = 256 = gridDim.y*BN)
        float4 wv = *reinterpret_cast<const float4*>(W + (size_t)(n0 + lr) * D + k0 + lc);

        __syncthreads();   // WAR: previous iteration's reads done before overwrite
        As[lc + 0][lr] = av.x;
        As[lc + 1][lr] = av.y;
        As[lc + 2][lr] = av.z;
        As[lc + 3][lr] = av.w;
        Bs[lc + 0][lr] = wv.x;
        Bs[lc + 1][lr] = wv.y;
        Bs[lc + 2][lr] = wv.z;
        Bs[lc + 3][lr] = wv.w;
        __syncthreads();

#pragma unroll
        for (int k = 0; k < BK; k++) {
            float a[4], bb[4];
#pragma unroll
            for (int i = 0; i < 4; i++) a[i] = As[k][ty * 4 + i];
#pragma unroll
            for (int j = 0; j < 4; j++) bb[j] = Bs[k][tx * 4 + j];
#pragma unroll
            for (int i = 0; i < 4; i++)
#pragma unroll
                for (int j = 0; j < 4; j++)
                    acc[i][j] = fmaf(a[i], bb[j], acc[i][j]);
        }
    }

    const float4 bl = *reinterpret_cast<const float4*>(b_lin + n0 + tx * 4);
#pragma unroll
    for (int i = 0; i < 4; i++) {
        const int m = m0 + ty * 4 + i;
        if (m < M) {
            float4 o;
            o.x = acc[i][0] + bl.x;
            o.y = acc[i][1] + bl.y;
            o.z = acc[i][2] + bl.z;
            o.w = acc[i][3] + bl.w;
            *reinterpret_cast<float4*>(g_support + (size_t)m * D + n0 + tx * 4) = o;
        }
    }
}

// ---------------------------------------------------------------------------
// Kernel 2: neighbor gather + multiply + sum + tanh + bias
// 4 nodes per 256-thread block; 64 threads per node; one float4 per thread.
// Index dtype (int64 vs int32) detected at runtime; indices clamped so a
// wrong guess yields a finite rel_err instead of an IMA.
// ---------------------------------------------------------------------------
__global__ __launch_bounds__(256)
void gather_kernel(const void* __restrict__ a2a_raw,
                   const void* __restrict__ n2e_raw,
                   const float* __restrict__ fedges,
                   const float* __restrict__ bias,
                   float* __restrict__ out)
{
    const int grp  = threadIdx.x >> 6;           // 0..3: node group within block
    const int lane = threadIdx.x & 63;           // 0..63: float4 index within D
    const int node = blockIdx.x * 4 + grp;       // grid = 50000/4 exactly

    __shared__ int sA[4][MAX_NEI];
    __shared__ int sE[4][MAX_NEI];
    __shared__ int s_is64a, s_is64e;

    // --- dtype probe: int64(LE, val<2^31) => all odd 32-bit words are zero ---
    if (threadIdx.x == 0) { s_is64a = 1; s_is64e = 1; }
    __syncthreads();
    {
        const unsigned* ua = (const unsigned*)a2a_raw;
        const unsigned* ue = (const unsigned*)n2e_raw;
        if (threadIdx.x < 64) {
            if (ua[2 * threadIdx.x + 1] != 0u) s_is64a = 0;   // benign race
        } else if (threadIdx.x < 128) {
            const int t = threadIdx.x - 64;
            if (ue[2 * t + 1] != 0u) s_is64e = 0;
        }
    }
    __syncthreads();
    const bool is64a = (s_is64a != 0);
    const bool is64e = (s_is64e != 0);

    // --- stage + clamp this group's 16+16 indices through shared ---
    if (lane < MAX_NEI) {
        long long v = is64a
            ? ((const long long*)a2a_raw)[(size_t)node * MAX_NEI + lane]
            : (long long)((const int*)a2a_raw)[(size_t)node * MAX_NEI + lane];
        if (v < 0) v = 0;
        if (v >= N_NODES) v = N_NODES - 1;
        sA[grp][lane] = (int)v;
    } else if (lane < 2 * MAX_NEI) {
        const int k = lane - MAX_NEI;
        long long v = is64e
            ? ((const long long*)n2e_raw)[(size_t)node * MAX_NEI + k]
            : (long long)((const int*)n2e_raw)[(size_t)node * MAX_NEI + k];
        if (v < 0) v = 0;
        if (v >= N_EDGES) v = N_EDGES - 1;
        sE[grp][lane - MAX_NEI] = (int)v;
    }
    __syncthreads();

    float ax = 0.f, ay = 0.f, az = 0.f, aw = 0.f;
    const int doff = lane * 4;

#pragma unroll
    for (int k = 0; k < MAX_NEI; k++) {
        const size_t ia = (size_t)sA[grp][k];
        const size_t ie = (size_t)sE[grp][k];
        const float4 a = *reinterpret_cast<const float4*>(g_support + ia * D + doff);
        const float4 e = *reinterpret_cast<const float4*>(fedges + ie * D + doff);
        ax = fmaf(a.x, e.x, ax);
        ay = fmaf(a.y, e.y, ay);
        az = fmaf(a.z, e.z, az);
        aw = fmaf(a.w, e.w, aw);
    }

    const float4 bv = *reinterpret_cast<const float4*>(bias + doff);
    float4 o;
    o.x = tanhf(ax) + bv.x;
    o.y = tanhf(ay) + bv.y;
    o.z = tanhf(az) + bv.z;
    o.w = tanhf(aw) + bv.w;
    *reinterpret_cast<float4*>(out + (size_t)node * D + doff) = o;
}

// ---------------------------------------------------------------------------
// Launch
// ---------------------------------------------------------------------------
extern "C" void kernel_launch(void* const* d_in, const int* in_sizes, int n_in,
                              void* d_out, int out_size)
{
    const float* X      = (const float*)d_in[0];  // [N_NODES, D]
    const float* fedges = (const float*)d_in[1];  // [N_EDGES, D]
    const void*  a2a    = d_in[2];                // [N_NODES, 16] int64 or int32
    const void*  n2e    = d_in[3];                // [N_NODES, 16] int64 or int32
    const float* W      = (const float*)d_in[4];  // [D, D]
    const float* b_lin  = (const float*)d_in[5];  // [D]
    const float* bias   = (const float*)d_in[6];  // [D]
    float* out = (float*)d_out;                   // [N_NODES, D]

    dim3 gg((N_NODES + BM - 1) / BM, D / BN);   // (782, 4)
    gemm_bias_kernel<<<gg, 256>>>(X, W, b_lin, N_NODES);

    gather_kernel<<<N_NODES / 4, 256>>>(a2a, n2e, fedges, bias, out);
}

// round 5
// speedup vs baseline: 1.1117x; 1.1117x over previous
#include <cuda_runtime.h>
#include <cuda_bf16.h>

// Problem constants (from reference)
#define N_NODES 50000
#define N_EDGES 800000
#define MAX_NEI 16
#define D 256

// Scratch for support = X @ W^T + b_lin (51.2 MB).
__device__ float g_support[(size_t)N_NODES * D];

// ---------------------------------------------------------------------------
// Kernel 1: tiled SGEMM  g_support[m,o] = sum_d X[m,d] * W[o,d] + b[o]
// BM=BN=128, BK=16, 256 threads, 8x8 micro-tile per thread.
// ---------------------------------------------------------------------------
#define BM 128
#define BN 128
#define BK 16
#define PAD 4   // 128+4=132 words/row: keeps 16B alignment (132*4=528=33*16)

__global__ __launch_bounds__(256)
void gemm_bias_kernel(const float* __restrict__ X,
                      const float* __restrict__ W,
                      const float* __restrict__ b_lin,
                      int M)
{
    __shared__ float As[BK][BM + PAD];   // As[k][m]
    __shared__ float Bs[BK][BN + PAD];   // Bs[k][o]

    const int tid = threadIdx.x;
    const int m0 = blockIdx.x * BM;
    const int n0 = blockIdx.y * BN;

    const int tx = tid & 15;    // 0..15 -> N direction (8 cols each)
    const int ty = tid >> 4;    // 0..15 -> M direction (8 rows each)

    // Load mapping: each thread owns row lr (0..127) and an 8-float half
    // (lh = 0 or 8) of the BK=16-wide K-slab. Warp = 32 consecutive lr with
    // identical lh -> conflict-free transpose stores (banks = lr % 32).
    const int lr = tid & 127;
    const int lh = (tid >> 7) * 8;

    float acc[8][8];
#pragma unroll
    for (int i = 0; i < 8; i++)
#pragma unroll
        for (int j = 0; j < 8; j++) acc[i][j] = 0.0f;

    for (int k0 = 0; k0 < D; k0 += BK) {
        const int gm = m0 + lr;
        float4 a0 = make_float4(0.f, 0.f, 0.f, 0.f);
        float4 a1 = make_float4(0.f, 0.f, 0.f, 0.f);
        if (gm < M) {
            a0 = *reinterpret_cast<const float4*>(X + (size_t)gm * D + k0 + lh);
            a1 = *reinterpret_cast<const float4*>(X + (size_t)gm * D + k0 + lh + 4);
        }
        // W rows n0+lr always in range (output dim 256 = gridDim.y * BN)
        const float4 w0 = *reinterpret_cast<const float4*>(W + (size_t)(n0 + lr) * D + k0 + lh);
        const float4 w1 = *reinterpret_cast<const float4*>(W + (size_t)(n0 + lr) * D + k0 + lh + 4);

        __syncthreads();   // WAR: previous iteration's reads done before overwrite
        As[lh + 0][lr] = a0.x;  As[lh + 1][lr] = a0.y;
        As[lh + 2][lr] = a0.z;  As[lh + 3][lr] = a0.w;
        As[lh + 4][lr] = a1.x;  As[lh + 5][lr] = a1.y;
        As[lh + 6][lr] = a1.z;  As[lh + 7][lr] = a1.w;
        Bs[lh + 0][lr] = w0.x;  Bs[lh + 1][lr] = w0.y;
        Bs[lh + 2][lr] = w0.z;  Bs[lh + 3][lr] = w0.w;
        Bs[lh + 4][lr] = w1.x;  Bs[lh + 5][lr] = w1.y;
        Bs[lh + 6][lr] = w1.z;  Bs[lh + 7][lr] = w1.w;
        __syncthreads();

#pragma unroll
        for (int k = 0; k < BK; k++) {
            float a[8], b[8];
            const float4 av0 = *reinterpret_cast<const float4*>(&As[k][ty * 8]);
            const float4 av1 = *reinterpret_cast<const float4*>(&As[k][ty * 8 + 4]);
            const float4 bv0 = *reinterpret_cast<const float4*>(&Bs[k][tx * 8]);
            const float4 bv1 = *reinterpret_cast<const float4*>(&Bs[k][tx * 8 + 4]);
            a[0] = av0.x; a[1] = av0.y; a[2] = av0.z; a[3] = av0.w;
            a[4] = av1.x; a[5] = av1.y; a[6] = av1.z; a[7] = av1.w;
            b[0] = bv0.x; b[1] = bv0.y; b[2] = bv0.z; b[3] = bv0.w;
            b[4] = bv1.x; b[5] = bv1.y; b[6] = bv1.z; b[7] = bv1.w;
#pragma unroll
            for (int i = 0; i < 8; i++)
#pragma unroll
                for (int j = 0; j < 8; j++)
                    acc[i][j] = fmaf(a[i], b[j], acc[i][j]);
        }
    }

    // Epilogue: bias + store (two float4 per row)
    const float4 bl0 = *reinterpret_cast<const float4*>(b_lin + n0 + tx * 8);
    const float4 bl1 = *reinterpret_cast<const float4*>(b_lin + n0 + tx * 8 + 4);
#pragma unroll
    for (int i = 0; i < 8; i++) {
        const int m = m0 + ty * 8 + i;
        if (m < M) {
            float4 o0, o1;
            o0.x = acc[i][0] + bl0.x;  o0.y = acc[i][1] + bl0.y;
            o0.z = acc[i][2] + bl0.z;  o0.w = acc[i][3] + bl0.w;
            o1.x = acc[i][4] + bl1.x;  o1.y = acc[i][5] + bl1.y;
            o1.z = acc[i][6] + bl1.z;  o1.w = acc[i][7] + bl1.w;
            *reinterpret_cast<float4*>(g_support + (size_t)m * D + n0 + tx * 8)     = o0;
            *reinterpret_cast<float4*>(g_support + (size_t)m * D + n0 + tx * 8 + 4) = o1;
        }
    }
}

// ---------------------------------------------------------------------------
// Kernel 2: neighbor gather + multiply + sum + tanh + bias  (81% DRAM — at
// roofline; unchanged from R4)
// ---------------------------------------------------------------------------
__global__ __launch_bounds__(256)
void gather_kernel(const void* __restrict__ a2a_raw,
                   const void* __restrict__ n2e_raw,
                   const float* __restrict__ fedges,
                   const float* __restrict__ bias,
                   float* __restrict__ out)
{
    const int grp  = threadIdx.x >> 6;           // 0..3: node group within block
    const int lane = threadIdx.x & 63;           // 0..63: float4 index within D
    const int node = blockIdx.x * 4 + grp;       // grid = 50000/4 exactly

    __shared__ int sA[4][MAX_NEI];
    __shared__ int sE[4][MAX_NEI];
    __shared__ int s_is64a, s_is64e;

    // dtype probe: int64(LE, val<2^31) => all odd 32-bit words are zero
    if (threadIdx.x == 0) { s_is64a = 1; s_is64e = 1; }
    __syncthreads();
    {
        const unsigned* ua = (const unsigned*)a2a_raw;
        const unsigned* ue = (const unsigned*)n2e_raw;
        if (threadIdx.x < 64) {
            if (ua[2 * threadIdx.x + 1] != 0u) s_is64a = 0;   // benign race
        } else if (threadIdx.x < 128) {
            const int t = threadIdx.x - 64;
            if (ue[2 * t + 1] != 0u) s_is64e = 0;
        }
    }
    __syncthreads();
    const bool is64a = (s_is64a != 0);
    const bool is64e = (s_is64e != 0);

    if (lane < MAX_NEI) {
        long long v = is64a
            ? ((const long long*)a2a_raw)[(size_t)node * MAX_NEI + lane]
            : (long long)((const int*)a2a_raw)[(size_t)node * MAX_NEI + lane];
        if (v < 0) v = 0;
        if (v >= N_NODES) v = N_NODES - 1;
        sA[grp][lane] = (int)v;
    } else if (lane < 2 * MAX_NEI) {
        const int k = lane - MAX_NEI;
        long long v = is64e
            ? ((const long long*)n2e_raw)[(size_t)node * MAX_NEI + k]
            : (long long)((const int*)n2e_raw)[(size_t)node * MAX_NEI + k];
        if (v < 0) v = 0;
        if (v >= N_EDGES) v = N_EDGES - 1;
        sE[grp][lane - MAX_NEI] = (int)v;
    }
    __syncthreads();

    float ax = 0.f, ay = 0.f, az = 0.f, aw = 0.f;
    const int doff = lane * 4;

#pragma unroll
    for (int k = 0; k < MAX_NEI; k++) {
        const size_t ia = (size_t)sA[grp][k];
        const size_t ie = (size_t)sE[grp][k];
        const float4 a = *reinterpret_cast<const float4*>(g_support + ia * D + doff);
        const float4 e = *reinterpret_cast<const float4*>(fedges + ie * D + doff);
        ax = fmaf(a.x, e.x, ax);
        ay = fmaf(a.y, e.y, ay);
        az = fmaf(a.z, e.z, az);
        aw = fmaf(a.w, e.w, aw);
    }

    const float4 bv = *reinterpret_cast<const float4*>(bias + doff);
    float4 o;
    o.x = tanhf(ax) + bv.x;
    o.y = tanhf(ay) + bv.y;
    o.z = tanhf(az) + bv.z;
    o.w = tanhf(aw) + bv.w;
    *reinterpret_cast<float4*>(out + (size_t)node * D + doff) = o;
}

// ---------------------------------------------------------------------------
// Launch
// ---------------------------------------------------------------------------
extern "C" void kernel_launch(void* const* d_in, const int* in_sizes, int n_in,
                              void* d_out, int out_size)
{
    const float* X      = (const float*)d_in[0];  // [N_NODES, D]
    const float* fedges = (const float*)d_in[1];  // [N_EDGES, D]
    const void*  a2a    = d_in[2];                // [N_NODES, 16] int64/int32
    const void*  n2e    = d_in[3];                // [N_NODES, 16] int64/int32
    const float* W      = (const float*)d_in[4];  // [D, D]
    const float* b_lin  = (const float*)d_in[5];  // [D]
    const float* bias   = (const float*)d_in[6];  // [D]
    float* out = (float*)d_out;                   // [N_NODES, D]

    dim3 gg((N_NODES + BM - 1) / BM, D / BN);   // (391, 2)
    gemm_bias_kernel<<<gg, 256>>>(X, W, b_lin, N_NODES);

    gather_kernel<<<N_NODES / 4, 256>>>(a2a, n2e, fedges, bias, out);
}

// round 6
// speedup vs baseline: 1.1910x; 1.0714x over previous
#include <cuda_runtime.h>
#include <cuda_bf16.h>

// Problem constants (from reference)
#define N_NODES 50000
#define N_EDGES 800000
#define MAX_NEI 16
#define D 256

// Scratch for support = X @ W^T + b_lin (51.2 MB).
__device__ float g_support[(size_t)N_NODES * D];

// ---- packed f32x2 helpers (sm_100+: 2 full-precision fp32 FMAs / instr) ----
__device__ __forceinline__ unsigned long long fma2(unsigned long long a,
                                                   unsigned long long b,
                                                   unsigned long long c)
{
    unsigned long long d;
    asm("fma.rn.f32x2 %0, %1, %2, %3;" : "=l"(d) : "l"(a), "l"(b), "l"(c));
    return d;
}

__device__ __forceinline__ unsigned long long pack_dup(float x)
{
    unsigned long long r;
    asm("mov.b64 %0, {%1, %1};" : "=l"(r) : "f"(x));
    return r;
}

__device__ __forceinline__ void unpack2(unsigned long long v, float& lo, float& hi)
{
    asm("mov.b64 {%0, %1}, %2;" : "=f"(lo), "=f"(hi) : "l"(v));
}

// ---------------------------------------------------------------------------
// Kernel 1: tiled SGEMM  g_support[m,o] = sum_d X[m,d] * W[o,d] + b[o]
// BM=BN=128, BK=16, 256 threads, 8x8 micro-tile, FFMA2-packed inner product.
// ---------------------------------------------------------------------------
#define BM 128
#define BN 128
#define BK 16
#define PAD 4   // 128+4=132 words/row keeps 16B alignment (528 = 33*16)

__global__ __launch_bounds__(256)
void gemm_bias_kernel(const float* __restrict__ X,
                      const float* __restrict__ W,
                      const float* __restrict__ b_lin,
                      int M)
{
    __shared__ float As[BK][BM + PAD];   // As[k][m]
    __shared__ float Bs[BK][BN + PAD];   // Bs[k][o]

    const int tid = threadIdx.x;
    const int m0 = blockIdx.x * BM;
    const int n0 = blockIdx.y * BN;

    const int tx = tid & 15;    // 0..15 -> N direction (8 cols each)
    const int ty = tid >> 4;    // 0..15 -> M direction (8 rows each)

    const int lr = tid & 127;            // row within tile (0..127)
    const int lh = (tid >> 7) * 8;       // which 8-float half of the K-slab

    // acc[i][j] holds output pair (2 columns) for row i: packed f32x2
    unsigned long long acc[8][4];
#pragma unroll
    for (int i = 0; i < 8; i++)
#pragma unroll
        for (int j = 0; j < 4; j++) acc[i][j] = 0ULL;

    for (int k0 = 0; k0 < D; k0 += BK) {
        const int gm = m0 + lr;
        float4 a0 = make_float4(0.f, 0.f, 0.f, 0.f);
        float4 a1 = make_float4(0.f, 0.f, 0.f, 0.f);
        if (gm < M) {
            a0 = *reinterpret_cast<const float4*>(X + (size_t)gm * D + k0 + lh);
            a1 = *reinterpret_cast<const float4*>(X + (size_t)gm * D + k0 + lh + 4);
        }
        const float4 w0 = *reinterpret_cast<const float4*>(W + (size_t)(n0 + lr) * D + k0 + lh);
        const float4 w1 = *reinterpret_cast<const float4*>(W + (size_t)(n0 + lr) * D + k0 + lh + 4);

        __syncthreads();   // WAR: previous iteration's reads done before overwrite
        As[lh + 0][lr] = a0.x;  As[lh + 1][lr] = a0.y;
        As[lh + 2][lr] = a0.z;  As[lh + 3][lr] = a0.w;
        As[lh + 4][lr] = a1.x;  As[lh + 5][lr] = a1.y;
        As[lh + 6][lr] = a1.z;  As[lh + 7][lr] = a1.w;
        Bs[lh + 0][lr] = w0.x;  Bs[lh + 1][lr] = w0.y;
        Bs[lh + 2][lr] = w0.z;  Bs[lh + 3][lr] = w0.w;
        Bs[lh + 4][lr] = w1.x;  Bs[lh + 5][lr] = w1.y;
        Bs[lh + 6][lr] = w1.z;  Bs[lh + 7][lr] = w1.w;
        __syncthreads();

#pragma unroll
        for (int k = 0; k < BK; k++) {
            // A fragment: 8 scalars
            const float4 av0 = *reinterpret_cast<const float4*>(&As[k][ty * 8]);
            const float4 av1 = *reinterpret_cast<const float4*>(&As[k][ty * 8 + 4]);
            float a[8];
            a[0] = av0.x; a[1] = av0.y; a[2] = av0.z; a[3] = av0.w;
            a[4] = av1.x; a[5] = av1.y; a[6] = av1.z; a[7] = av1.w;

            // B fragment: 4 packed pairs (tx*8 floats = 32B aligned)
            const ulonglong2 bp0 = *reinterpret_cast<const ulonglong2*>(&Bs[k][tx * 8]);
            const ulonglong2 bp1 = *reinterpret_cast<const ulonglong2*>(&Bs[k][tx * 8 + 4]);
            const unsigned long long b0 = bp0.x, b1 = bp0.y, b2 = bp1.x, b3 = bp1.y;

#pragma unroll
            for (int i = 0; i < 8; i++) {
                const unsigned long long ai = pack_dup(a[i]);
                acc[i][0] = fma2(ai, b0, acc[i][0]);
                acc[i][1] = fma2(ai, b1, acc[i][1]);
                acc[i][2] = fma2(ai, b2, acc[i][2]);
                acc[i][3] = fma2(ai, b3, acc[i][3]);
            }
        }
    }

    // Epilogue: unpack, add bias, store 2 float4 per row
    const float4 bl0 = *reinterpret_cast<const float4*>(b_lin + n0 + tx * 8);
    const float4 bl1 = *reinterpret_cast<const float4*>(b_lin + n0 + tx * 8 + 4);
#pragma unroll
    for (int i = 0; i < 8; i++) {
        const int m = m0 + ty * 8 + i;
        if (m < M) {
            float c[8];
            unpack2(acc[i][0], c[0], c[1]);
            unpack2(acc[i][1], c[2], c[3]);
            unpack2(acc[i][2], c[4], c[5]);
            unpack2(acc[i][3], c[6], c[7]);
            float4 o0, o1;
            o0.x = c[0] + bl0.x;  o0.y = c[1] + bl0.y;
            o0.z = c[2] + bl0.z;  o0.w = c[3] + bl0.w;
            o1.x = c[4] + bl1.x;  o1.y = c[5] + bl1.y;
            o1.z = c[6] + bl1.z;  o1.w = c[7] + bl1.w;
            *reinterpret_cast<float4*>(g_support + (size_t)m * D + n0 + tx * 8)     = o0;
            *reinterpret_cast<float4*>(g_support + (size_t)m * D + n0 + tx * 8 + 4) = o1;
        }
    }
}

// ---------------------------------------------------------------------------
// Kernel 2: neighbor gather + multiply + sum + tanh + bias
// fedges streamed with __ldcs (evict-first) so the 51 MB support table stays
// L2-resident (measured ~200 MB of avoidable support DRAM re-fetches in R5).
// ---------------------------------------------------------------------------
__global__ __launch_bounds__(256)
void gather_kernel(const void* __restrict__ a2a_raw,
                   const void* __restrict__ n2e_raw,
                   const float* __restrict__ fedges,
                   const float* __restrict__ bias,
                   float* __restrict__ out)
{
    const int grp  = threadIdx.x >> 6;           // 0..3: node group within block
    const int lane = threadIdx.x & 63;           // 0..63: float4 index within D
    const int node = blockIdx.x * 4 + grp;       // grid = 50000/4 exactly

    __shared__ int sA[4][MAX_NEI];
    __shared__ int sE[4][MAX_NEI];
    __shared__ int s_is64a, s_is64e;

    // dtype probe: int64(LE, val<2^31) => all odd 32-bit words are zero
    if (threadIdx.x == 0) { s_is64a = 1; s_is64e = 1; }
    __syncthreads();
    {
        const unsigned* ua = (const unsigned*)a2a_raw;
        const unsigned* ue = (const unsigned*)n2e_raw;
        if (threadIdx.x < 64) {
            if (ua[2 * threadIdx.x + 1] != 0u) s_is64a = 0;   // benign race
        } else if (threadIdx.x < 128) {
            const int t = threadIdx.x - 64;
            if (ue[2 * t + 1] != 0u) s_is64e = 0;
        }
    }
    __syncthreads();
    const bool is64a = (s_is64a != 0);
    const bool is64e = (s_is64e != 0);

    if (lane < MAX_NEI) {
        long long v = is64a
            ? ((const long long*)a2a_raw)[(size_t)node * MAX_NEI + lane]
            : (long long)((const int*)a2a_raw)[(size_t)node * MAX_NEI + lane];
        if (v < 0) v = 0;
        if (v >= N_NODES) v = N_NODES - 1;
        sA[grp][lane] = (int)v;
    } else if (lane < 2 * MAX_NEI) {
        const int k = lane - MAX_NEI;
        long long v = is64e
            ? ((const long long*)n2e_raw)[(size_t)node * MAX_NEI + k]
            : (long long)((const int*)n2e_raw)[(size_t)node * MAX_NEI + k];
        if (v < 0) v = 0;
        if (v >= N_EDGES) v = N_EDGES - 1;
        sE[grp][lane - MAX_NEI] = (int)v;
    }
    __syncthreads();

    float ax = 0.f, ay = 0.f, az = 0.f, aw = 0.f;
    const int doff = lane * 4;

#pragma unroll
    for (int k = 0; k < MAX_NEI; k++) {
        const size_t ia = (size_t)sA[grp][k];
        const size_t ie = (size_t)sE[grp][k];
        const float4 a = *reinterpret_cast<const float4*>(g_support + ia * D + doff);
        const float4 e = __ldcs(reinterpret_cast<const float4*>(fedges + ie * D + doff));
        ax = fmaf(a.x, e.x, ax);
        ay = fmaf(a.y, e.y, ay);
        az = fmaf(a.z, e.z, az);
        aw = fmaf(a.w, e.w, aw);
    }

    const float4 bv = *reinterpret_cast<const float4*>(bias + doff);
    float4 o;
    o.x = tanhf(ax) + bv.x;
    o.y = tanhf(ay) + bv.y;
    o.z = tanhf(az) + bv.z;
    o.w = tanhf(aw) + bv.w;
    *reinterpret_cast<float4*>(out + (size_t)node * D + doff) = o;
}

// ---------------------------------------------------------------------------
// Launch
// ---------------------------------------------------------------------------
extern "C" void kernel_launch(void* const* d_in, const int* in_sizes, int n_in,
                              void* d_out, int out_size)
{
    const float* X      = (const float*)d_in[0];  // [N_NODES, D]
    const float* fedges = (const float*)d_in[1];  // [N_EDGES, D]
    const void*  a2a    = d_in[2];                // [N_NODES, 16] int64/int32
    const void*  n2e    = d_in[3];                // [N_NODES, 16] int64/int32
    const float* W      = (const float*)d_in[4];  // [D, D]
    const float* b_lin  = (const float*)d_in[5];  // [D]
    const float* bias   = (const float*)d_in[6];  // [D]
    float* out = (float*)d_out;                   // [N_NODES, D]

    dim3 gg((N_NODES + BM - 1) / BM, D / BN);   // (391, 2)
    gemm_bias_kernel<<<gg, 256>>>(X, W, b_lin, N_NODES);

    gather_kernel<<<N_NODES / 4, 256>>>(a2a, n2e, fedges, bias, out);
}

// round 7
// speedup vs baseline: 1.1992x; 1.0069x over previous
#include <cuda_runtime.h>
#include <cuda_bf16.h>

// Problem constants (from reference)
#define N_NODES 50000
#define N_EDGES 800000
#define MAX_NEI 16
#define D 256

// Scratch for support = X @ W^T + b_lin (51.2 MB).
__device__ float g_support[(size_t)N_NODES * D];

// ---- packed f32x2 helpers (sm_100+: 2 full-precision fp32 FMAs / instr) ----
__device__ __forceinline__ unsigned long long fma2(unsigned long long a,
                                                   unsigned long long b,
                                                   unsigned long long c)
{
    unsigned long long d;
    asm("fma.rn.f32x2 %0, %1, %2, %3;" : "=l"(d) : "l"(a), "l"(b), "l"(c));
    return d;
}

__device__ __forceinline__ unsigned long long pack_dup(float x)
{
    unsigned long long r;
    asm("mov.b64 %0, {%1, %1};" : "=l"(r) : "f"(x));
    return r;
}

__device__ __forceinline__ void unpack2(unsigned long long v, float& lo, float& hi)
{
    asm("mov.b64 {%0, %1}, %2;" : "=f"(lo), "=f"(hi) : "l"(v));
}

// ---------------------------------------------------------------------------
// Kernel 1: tiled SGEMM  g_support[m,o] = sum_d X[m,d] * W[o,d] + b[o]
// BM=BN=128, BK=16, 256 threads, 8x8 micro-tile, FFMA2 inner product,
// double-buffered smem + register prefetch (one barrier per K-tile).
// ---------------------------------------------------------------------------
#define BM 128
#define BN 128
#define BK 16
#define PAD 4   // 128+4=132 words/row keeps 16B alignment (528 = 33*16)

__global__ __launch_bounds__(256, 2)
void gemm_bias_kernel(const float* __restrict__ X,
                      const float* __restrict__ W,
                      const float* __restrict__ b_lin,
                      int M)
{
    __shared__ float As[2][BK][BM + PAD];   // As[buf][k][m]
    __shared__ float Bs[2][BK][BN + PAD];   // Bs[buf][k][o]

    const int tid = threadIdx.x;
    const int m0 = blockIdx.x * BM;
    const int n0 = blockIdx.y * BN;

    const int tx = tid & 15;    // 0..15 -> N direction (8 cols each)
    const int ty = tid >> 4;    // 0..15 -> M direction (8 rows each)

    const int lr = tid & 127;            // row within tile (0..127)
    const int lh = (tid >> 7) * 8;       // which 8-float half of the K-slab
    const int gm = m0 + lr;
    const bool arow_ok = (gm < M);
    const float* Arow = X + (size_t)gm * D + lh;
    const float* Wrow = W + (size_t)(n0 + lr) * D + lh;

    unsigned long long acc[8][4];   // [row][col-pair], packed f32x2
#pragma unroll
    for (int i = 0; i < 8; i++)
#pragma unroll
        for (int j = 0; j < 4; j++) acc[i][j] = 0ULL;

    // ---- prologue: load tile 0 ----
    float4 a0 = make_float4(0.f, 0.f, 0.f, 0.f);
    float4 a1 = a0;
    if (arow_ok) {
        a0 = *reinterpret_cast<const float4*>(Arow);
        a1 = *reinterpret_cast<const float4*>(Arow + 4);
    }
    float4 w0 = *reinterpret_cast<const float4*>(Wrow);
    float4 w1 = *reinterpret_cast<const float4*>(Wrow + 4);

    {
        As[0][lh + 0][lr] = a0.x;  As[0][lh + 1][lr] = a0.y;
        As[0][lh + 2][lr] = a0.z;  As[0][lh + 3][lr] = a0.w;
        As[0][lh + 4][lr] = a1.x;  As[0][lh + 5][lr] = a1.y;
        As[0][lh + 6][lr] = a1.z;  As[0][lh + 7][lr] = a1.w;
        Bs[0][lh + 0][lr] = w0.x;  Bs[0][lh + 1][lr] = w0.y;
        Bs[0][lh + 2][lr] = w0.z;  Bs[0][lh + 3][lr] = w0.w;
        Bs[0][lh + 4][lr] = w1.x;  Bs[0][lh + 5][lr] = w1.y;
        Bs[0][lh + 6][lr] = w1.z;  Bs[0][lh + 7][lr] = w1.w;
    }
    __syncthreads();

    const int NT = D / BK;   // 16 K-tiles
#pragma unroll 1
    for (int t = 0; t < NT; t++) {
        const int buf = t & 1;

        // prefetch next tile into registers (latency hidden by compute below)
        if (t + 1 < NT) {
            const int k0 = (t + 1) * BK;
            if (arow_ok) {
                a0 = *reinterpret_cast<const float4*>(Arow + k0);
                a1 = *reinterpret_cast<const float4*>(Arow + k0 + 4);
            }
            w0 = *reinterpret_cast<const float4*>(Wrow + k0);
            w1 = *reinterpret_cast<const float4*>(Wrow + k0 + 4);
        }

        // compute on current buffer
#pragma unroll
        for (int k = 0; k < BK; k++) {
            const float4 av0 = *reinterpret_cast<const float4*>(&As[buf][k][ty * 8]);
            const float4 av1 = *reinterpret_cast<const float4*>(&As[buf][k][ty * 8 + 4]);
            const ulonglong2 bp0 = *reinterpret_cast<const ulonglong2*>(&Bs[buf][k][tx * 8]);
            const ulonglong2 bp1 = *reinterpret_cast<const ulonglong2*>(&Bs[buf][k][tx * 8 + 4]);
            float a[8];
            a[0] = av0.x; a[1] = av0.y; a[2] = av0.z; a[3] = av0.w;
            a[4] = av1.x; a[5] = av1.y; a[6] = av1.z; a[7] = av1.w;
            const unsigned long long b0 = bp0.x, b1 = bp0.y, b2 = bp1.x, b3 = bp1.y;
#pragma unroll
            for (int i = 0; i < 8; i++) {
                const unsigned long long ai = pack_dup(a[i]);
                acc[i][0] = fma2(ai, b0, acc[i][0]);
                acc[i][1] = fma2(ai, b1, acc[i][1]);
                acc[i][2] = fma2(ai, b2, acc[i][2]);
                acc[i][3] = fma2(ai, b3, acc[i][3]);
            }
        }

        // store prefetched tile into the other buffer; single barrier
        if (t + 1 < NT) {
            const int nb = buf ^ 1;
            As[nb][lh + 0][lr] = a0.x;  As[nb][lh + 1][lr] = a0.y;
            As[nb][lh + 2][lr] = a0.z;  As[nb][lh + 3][lr] = a0.w;
            As[nb][lh + 4][lr] = a1.x;  As[nb][lh + 5][lr] = a1.y;
            As[nb][lh + 6][lr] = a1.z;  As[nb][lh + 7][lr] = a1.w;
            Bs[nb][lh + 0][lr] = w0.x;  Bs[nb][lh + 1][lr] = w0.y;
            Bs[nb][lh + 2][lr] = w0.z;  Bs[nb][lh + 3][lr] = w0.w;
            Bs[nb][lh + 4][lr] = w1.x;  Bs[nb][lh + 5][lr] = w1.y;
            Bs[nb][lh + 6][lr] = w1.z;  Bs[nb][lh + 7][lr] = w1.w;
            __syncthreads();
        }
    }

    // Epilogue: unpack, add bias, store 2 float4 per row
    const float4 bl0 = *reinterpret_cast<const float4*>(b_lin + n0 + tx * 8);
    const float4 bl1 = *reinterpret_cast<const float4*>(b_lin + n0 + tx * 8 + 4);
#pragma unroll
    for (int i = 0; i < 8; i++) {
        const int m = m0 + ty * 8 + i;
        if (m < M) {
            float c[8];
            unpack2(acc[i][0], c[0], c[1]);
            unpack2(acc[i][1], c[2], c[3]);
            unpack2(acc[i][2], c[4], c[5]);
            unpack2(acc[i][3], c[6], c[7]);
            float4 o0, o1;
            o0.x = c[0] + bl0.x;  o0.y = c[1] + bl0.y;
            o0.z = c[2] + bl0.z;  o0.w = c[3] + bl0.w;
            o1.x = c[4] + bl1.x;  o1.y = c[5] + bl1.y;
            o1.z = c[6] + bl1.z;  o1.w = c[7] + bl1.w;
            *reinterpret_cast<float4*>(g_support + (size_t)m * D + n0 + tx * 8)     = o0;
            *reinterpret_cast<float4*>(g_support + (size_t)m * D + n0 + tx * 8 + 4) = o1;
        }
    }
}

// ---------------------------------------------------------------------------
// Kernel 2: neighbor gather + multiply + sum + tanh + bias
// fedges via __ldcs (evict-first stream), out via __stcs (write-once) so the
// 51 MB support table stays L2-resident.
// ---------------------------------------------------------------------------
__global__ __launch_bounds__(256)
void gather_kernel(const void* __restrict__ a2a_raw,
                   const void* __restrict__ n2e_raw,
                   const float* __restrict__ fedges,
                   const float* __restrict__ bias,
                   float* __restrict__ out)
{
    const int grp  = threadIdx.x >> 6;           // 0..3: node group within block
    const int lane = threadIdx.x & 63;           // 0..63: float4 index within D
    const int node = blockIdx.x * 4 + grp;       // grid = 50000/4 exactly

    __shared__ int sA[4][MAX_NEI];
    __shared__ int sE[4][MAX_NEI];
    __shared__ int s_is64a, s_is64e;

    // dtype probe: int64(LE, val<2^31) => all odd 32-bit words are zero
    if (threadIdx.x == 0) { s_is64a = 1; s_is64e = 1; }
    __syncthreads();
    {
        const unsigned* ua = (const unsigned*)a2a_raw;
        const unsigned* ue = (const unsigned*)n2e_raw;
        if (threadIdx.x < 64) {
            if (ua[2 * threadIdx.x + 1] != 0u) s_is64a = 0;   // benign race
        } else if (threadIdx.x < 128) {
            const int t = threadIdx.x - 64;
            if (ue[2 * t + 1] != 0u) s_is64e = 0;
        }
    }
    __syncthreads();
    const bool is64a = (s_is64a != 0);
    const bool is64e = (s_is64e != 0);

    if (lane < MAX_NEI) {
        long long v = is64a
            ? ((const long long*)a2a_raw)[(size_t)node * MAX_NEI + lane]
            : (long long)((const int*)a2a_raw)[(size_t)node * MAX_NEI + lane];
        if (v < 0) v = 0;
        if (v >= N_NODES) v = N_NODES - 1;
        sA[grp][lane] = (int)v;
    } else if (lane < 2 * MAX_NEI) {
        const int k = lane - MAX_NEI;
        long long v = is64e
            ? ((const long long*)n2e_raw)[(size_t)node * MAX_NEI + k]
            : (long long)((const int*)n2e_raw)[(size_t)node * MAX_NEI + k];
        if (v < 0) v = 0;
        if (v >= N_EDGES) v = N_EDGES - 1;
        sE[grp][lane - MAX_NEI] = (int)v;
    }
    __syncthreads();

    float ax = 0.f, ay = 0.f, az = 0.f, aw = 0.f;
    const int doff = lane * 4;

#pragma unroll
    for (int k = 0; k < MAX_NEI; k++) {
        const size_t ia = (size_t)sA[grp][k];
        const size_t ie = (size_t)sE[grp][k];
        const float4 a = *reinterpret_cast<const float4*>(g_support + ia * D + doff);
        const float4 e = __ldcs(reinterpret_cast<const float4*>(fedges + ie * D + doff));
        ax = fmaf(a.x, e.x, ax);
        ay = fmaf(a.y, e.y, ay);
        az = fmaf(a.z, e.z, az);
        aw = fmaf(a.w, e.w, aw);
    }

    const float4 bv = *reinterpret_cast<const float4*>(bias + doff);
    float4 o;
    o.x = tanhf(ax) + bv.x;
    o.y = tanhf(ay) + bv.y;
    o.z = tanhf(az) + bv.z;
    o.w = tanhf(aw) + bv.w;
    __stcs(reinterpret_cast<float4*>(out + (size_t)node * D + doff), o);
}

// ---------------------------------------------------------------------------
// Launch
// ---------------------------------------------------------------------------
extern "C" void kernel_launch(void* const* d_in, const int* in_sizes, int n_in,
                              void* d_out, int out_size)
{
    const float* X      = (const float*)d_in[0];  // [N_NODES, D]
    const float* fedges = (const float*)d_in[1];  // [N_EDGES, D]
    const void*  a2a    = d_in[2];                // [N_NODES, 16] int64/int32
    const void*  n2e    = d_in[3];                // [N_NODES, 16] int64/int32
    const float* W      = (const float*)d_in[4];  // [D, D]
    const float* b_lin  = (const float*)d_in[5];  // [D]
    const float* bias   = (const float*)d_in[6];  // [D]
    float* out = (float*)d_out;                   // [N_NODES, D]

    dim3 gg((N_NODES + BM - 1) / BM, D / BN);   // (391, 2)
    gemm_bias_kernel<<<gg, 256>>>(X, W, b_lin, N_NODES);

    gather_kernel<<<N_NODES / 4, 256>>>(a2a, n2e, fedges, bias, out);
}

// round 9
// speedup vs baseline: 1.6971x; 1.4152x over previous
#include <cuda_runtime.h>
#include <cuda_bf16.h>
#include <cstdint>

// Problem constants (from reference)
#define N_NODES 50000
#define N_EDGES 800000
#define MAX_NEI 16
#define D 256

// Static device scratch (allocation-free rule). Kernels reference symbols
// directly — no host-side symbol address lookups.
__device__ float         g_support[(size_t)N_NODES * D];  // 51.2 MB
__device__ __nv_bfloat16 g_xhi[(size_t)N_NODES * D];      // 25.6 MB
__device__ __nv_bfloat16 g_xlo[(size_t)N_NODES * D];      // 25.6 MB
__device__ __nv_bfloat16 g_whi[D * D];
__device__ __nv_bfloat16 g_wlo[D * D];

// ---------------------------------------------------------------------------
// helpers
// ---------------------------------------------------------------------------
__device__ __forceinline__ uint32_t smem_u32(const void* p) {
    uint32_t a;
    asm("{ .reg .u64 t; cvta.to.shared.u64 t, %1; cvt.u32.u64 %0, t; }"
        : "=r"(a) : "l"(p));
    return a;
}

__device__ __forceinline__ void ldsm_x4(uint32_t& r0, uint32_t& r1,
                                        uint32_t& r2, uint32_t& r3, uint32_t addr) {
    asm volatile("ldmatrix.sync.aligned.m8n8.x4.shared.b16 {%0,%1,%2,%3}, [%4];"
                 : "=r"(r0), "=r"(r1), "=r"(r2), "=r"(r3) : "r"(addr));
}

__device__ __forceinline__ void mma_bf16(float* c,
                                         uint32_t a0, uint32_t a1, uint32_t a2, uint32_t a3,
                                         uint32_t b0, uint32_t b1) {
    asm volatile(
        "mma.sync.aligned.m16n8k16.row.col.f32.bf16.bf16.f32 "
        "{%0,%1,%2,%3}, {%4,%5,%6,%7}, {%8,%9}, {%0,%1,%2,%3};"
        : "+f"(c[0]), "+f"(c[1]), "+f"(c[2]), "+f"(c[3])
        : "r"(a0), "r"(a1), "r"(a2), "r"(a3), "r"(b0), "r"(b1));
}

// ---------------------------------------------------------------------------
// Kernel 0a/0b: fp32 -> bf16 hi/lo split (x = hi + lo)
// ---------------------------------------------------------------------------
__global__ __launch_bounds__(256)
void split_x_kernel(const float* __restrict__ src, int n4)
{
    const int i = blockIdx.x * 256 + threadIdx.x;
    if (i >= n4) return;
    const float4 v = reinterpret_cast<const float4*>(src)[i];
    __nv_bfloat16 h[4], l[4];
    const float f[4] = {v.x, v.y, v.z, v.w};
#pragma unroll
    for (int j = 0; j < 4; j++) {
        h[j] = __float2bfloat16(f[j]);
        l[j] = __float2bfloat16(f[j] - __bfloat162float(h[j]));
    }
    reinterpret_cast<__nv_bfloat162*>(g_xhi)[2 * i]     = __halves2bfloat162(h[0], h[1]);
    reinterpret_cast<__nv_bfloat162*>(g_xhi)[2 * i + 1] = __halves2bfloat162(h[2], h[3]);
    reinterpret_cast<__nv_bfloat162*>(g_xlo)[2 * i]     = __halves2bfloat162(l[0], l[1]);
    reinterpret_cast<__nv_bfloat162*>(g_xlo)[2 * i + 1] = __halves2bfloat162(l[2], l[3]);
}

__global__ __launch_bounds__(256)
void split_w_kernel(const float* __restrict__ src, int n4)
{
    const int i = blockIdx.x * 256 + threadIdx.x;
    if (i >= n4) return;
    const float4 v = reinterpret_cast<const float4*>(src)[i];
    __nv_bfloat16 h[4], l[4];
    const float f[4] = {v.x, v.y, v.z, v.w};
#pragma unroll
    for (int j = 0; j < 4; j++) {
        h[j] = __float2bfloat16(f[j]);
        l[j] = __float2bfloat16(f[j] - __bfloat162float(h[j]));
    }
    reinterpret_cast<__nv_bfloat162*>(g_whi)[2 * i]     = __halves2bfloat162(h[0], h[1]);
    reinterpret_cast<__nv_bfloat162*>(g_whi)[2 * i + 1] = __halves2bfloat162(h[2], h[3]);
    reinterpret_cast<__nv_bfloat162*>(g_wlo)[2 * i]     = __halves2bfloat162(l[0], l[1]);
    reinterpret_cast<__nv_bfloat162*>(g_wlo)[2 * i + 1] = __halves2bfloat162(l[2], l[3]);
}

// ---------------------------------------------------------------------------
// Kernel 1: HMMA (mma.sync bf16) 3-term split GEMM
// support[m,o] = sum_k X[m,k] W[o,k] + b[o]
// CTA 128x128, BK=32, 8 warps (4 along M x 2 along N), warp tile 32x64.
// ---------------------------------------------------------------------------
#define BM 128
#define BN 128
#define BK 32
#define SROW 40   // smem row stride in bf16 (80 B) -> conflict-free ldmatrix

__global__ __launch_bounds__(256, 2)
void gemm_mma_kernel(const float* __restrict__ b_lin, int M)
{
    __shared__ __align__(16) __nv_bfloat16 sAh[BM][SROW];
    __shared__ __align__(16) __nv_bfloat16 sAl[BM][SROW];
    __shared__ __align__(16) __nv_bfloat16 sBh[BN][SROW];
    __shared__ __align__(16) __nv_bfloat16 sBl[BN][SROW];

    const int tid  = threadIdx.x;
    const int wid  = tid >> 5;
    const int lane = tid & 31;
    const int wm   = wid & 3;     // warp row: 4 x 32 rows
    const int wn   = wid >> 2;    // warp col: 2 x 64 cols
    const int m0   = blockIdx.x * BM;
    const int n0   = blockIdx.y * BN;

    const uint32_t sAh_b = smem_u32(sAh);
    const uint32_t sAl_b = smem_u32(sAl);
    const uint32_t sBh_b = smem_u32(sBh);
    const uint32_t sBl_b = smem_u32(sBl);

    float acc[2][8][4];
#pragma unroll
    for (int mt = 0; mt < 2; mt++)
#pragma unroll
        for (int nf = 0; nf < 8; nf++)
#pragma unroll
            for (int c = 0; c < 4; c++) acc[mt][nf][c] = 0.0f;

    // ldmatrix address components (lane-dependent, loop-invariant)
    const int a_row = (lane & 15);                 // + warp/tile base
    const int a_kb  = (lane >> 4) << 3;            // 0 or 8
    const int b_nrw = ((lane >> 4) << 3) + (lane & 7);
    const int b_kb  = ((lane >> 3) & 1) << 3;

    const int NT = D / BK;   // 8
#pragma unroll 1
    for (int t = 0; t < NT; t++) {
        const int kc = t * BK;

        __syncthreads();   // WAR on previous iteration's smem reads
        // each thread: 2 tasks x 4 matrices; task = 16B segment
#pragma unroll
        for (int j = 0; j < 2; j++) {
            const int idx = tid + j * 256;         // 0..511
            const int r = idx >> 2;                // 0..127
            const int s = (idx & 3) * 8;           // bf16 offset within BK
            const int gm = m0 + r;
            uint4 vh = make_uint4(0, 0, 0, 0), vl = vh;
            if (gm < M) {
                vh = *reinterpret_cast<const uint4*>(g_xhi + (size_t)gm * D + kc + s);
                vl = *reinterpret_cast<const uint4*>(g_xlo + (size_t)gm * D + kc + s);
            }
            *reinterpret_cast<uint4*>(&sAh[r][s]) = vh;
            *reinterpret_cast<uint4*>(&sAl[r][s]) = vl;
            *reinterpret_cast<uint4*>(&sBh[r][s]) =
                *reinterpret_cast<const uint4*>(g_whi + (size_t)(n0 + r) * D + kc + s);
            *reinterpret_cast<uint4*>(&sBl[r][s]) =
                *reinterpret_cast<const uint4*>(g_wlo + (size_t)(n0 + r) * D + kc + s);
        }
        __syncthreads();

#pragma unroll
        for (int ks = 0; ks < 2; ks++) {
            const int kb = ks * 16;

            // A fragments (hi and lo): 2 m16 tiles each
            uint32_t Ah[2][4], Al[2][4];
#pragma unroll
            for (int mt = 0; mt < 2; mt++) {
                const int row = wm * 32 + mt * 16 + a_row;
                const uint32_t off = (uint32_t)(row * (SROW * 2) + (kb + a_kb) * 2);
                ldsm_x4(Ah[mt][0], Ah[mt][1], Ah[mt][2], Ah[mt][3], sAh_b + off);
                ldsm_x4(Al[mt][0], Al[mt][1], Al[mt][2], Al[mt][3], sAl_b + off);
            }

            // B fragments: 8 n8 tiles; one x4 covers 2 tiles
            uint32_t Bb[8][2];
#pragma unroll
            for (int p = 0; p < 4; p++) {
                const int nrow = wn * 64 + p * 16 + b_nrw;
                const uint32_t off = (uint32_t)(nrow * (SROW * 2) + (kb + b_kb) * 2);
                ldsm_x4(Bb[2 * p][0], Bb[2 * p][1], Bb[2 * p + 1][0], Bb[2 * p + 1][1],
                        sBh_b + off);
            }
            // term 1: hi*hi ; term 2: lo*hi
#pragma unroll
            for (int mt = 0; mt < 2; mt++)
#pragma unroll
                for (int nf = 0; nf < 8; nf++)
                    mma_bf16(acc[mt][nf], Ah[mt][0], Ah[mt][1], Ah[mt][2], Ah[mt][3],
                             Bb[nf][0], Bb[nf][1]);
#pragma unroll
            for (int mt = 0; mt < 2; mt++)
#pragma unroll
                for (int nf = 0; nf < 8; nf++)
                    mma_bf16(acc[mt][nf], Al[mt][0], Al[mt][1], Al[mt][2], Al[mt][3],
                             Bb[nf][0], Bb[nf][1]);
            // reload B with lo; term 3: hi*lo
#pragma unroll
            for (int p = 0; p < 4; p++) {
                const int nrow = wn * 64 + p * 16 + b_nrw;
                const uint32_t off = (uint32_t)(nrow * (SROW * 2) + (kb + b_kb) * 2);
                ldsm_x4(Bb[2 * p][0], Bb[2 * p][1], Bb[2 * p + 1][0], Bb[2 * p + 1][1],
                        sBl_b + off);
            }
#pragma unroll
            for (int mt = 0; mt < 2; mt++)
#pragma unroll
                for (int nf = 0; nf < 8; nf++)
                    mma_bf16(acc[mt][nf], Ah[mt][0], Ah[mt][1], Ah[mt][2], Ah[mt][3],
                             Bb[nf][0], Bb[nf][1]);
        }
    }

    // Epilogue: accum fragment (lane l: c0,c1 @ (row=l/4, col=2(l%4)); c2,c3 @ row+8)
    const int erow = lane >> 2;
    const int ecol = (lane & 3) * 2;
#pragma unroll
    for (int nf = 0; nf < 8; nf++) {
        const int col = n0 + wn * 64 + nf * 8 + ecol;
        const float2 bl = *reinterpret_cast<const float2*>(b_lin + col);
#pragma unroll
        for (int mt = 0; mt < 2; mt++) {
            const int r0 = m0 + wm * 32 + mt * 16 + erow;
            if (r0 < M) {
                float2 o;
                o.x = acc[mt][nf][0] + bl.x;
                o.y = acc[mt][nf][1] + bl.y;
                *reinterpret_cast<float2*>(g_support + (size_t)r0 * D + col) = o;
            }
            if (r0 + 8 < M) {
                float2 o;
                o.x = acc[mt][nf][2] + bl.x;
                o.y = acc[mt][nf][3] + bl.y;
                *reinterpret_cast<float2*>(g_support + (size_t)(r0 + 8) * D + col) = o;
            }
        }
    }
}

// ---------------------------------------------------------------------------
// Kernel 2: neighbor gather + multiply + sum + tanh + bias (at DRAM roofline)
// ---------------------------------------------------------------------------
__global__ __launch_bounds__(256)
void gather_kernel(const void* __restrict__ a2a_raw,
                   const void* __restrict__ n2e_raw,
                   const float* __restrict__ fedges,
                   const float* __restrict__ bias,
                   float* __restrict__ out)
{
    const int grp  = threadIdx.x >> 6;
    const int lane = threadIdx.x & 63;
    const int node = blockIdx.x * 4 + grp;

    __shared__ int sA[4][MAX_NEI];
    __shared__ int sE[4][MAX_NEI];
    __shared__ int s_is64a, s_is64e;

    if (threadIdx.x == 0) { s_is64a = 1; s_is64e = 1; }
    __syncthreads();
    {
        const unsigned* ua = (const unsigned*)a2a_raw;
        const unsigned* ue = (const unsigned*)n2e_raw;
        if (threadIdx.x < 64) {
            if (ua[2 * threadIdx.x + 1] != 0u) s_is64a = 0;   // benign race
        } else if (threadIdx.x < 128) {
            const int t = threadIdx.x - 64;
            if (ue[2 * t + 1] != 0u) s_is64e = 0;
        }
    }
    __syncthreads();
    const bool is64a = (s_is64a != 0);
    const bool is64e = (s_is64e != 0);

    if (lane < MAX_NEI) {
        long long v = is64a
            ? ((const long long*)a2a_raw)[(size_t)node * MAX_NEI + lane]
            : (long long)((const int*)a2a_raw)[(size_t)node * MAX_NEI + lane];
        if (v < 0) v = 0;
        if (v >= N_NODES) v = N_NODES - 1;
        sA[grp][lane] = (int)v;
    } else if (lane < 2 * MAX_NEI) {
        const int k = lane - MAX_NEI;
        long long v = is64e
            ? ((const long long*)n2e_raw)[(size_t)node * MAX_NEI + k]
            : (long long)((const int*)n2e_raw)[(size_t)node * MAX_NEI + k];
        if (v < 0) v = 0;
        if (v >= N_EDGES) v = N_EDGES - 1;
        sE[grp][lane - MAX_NEI] = (int)v;
    }
    __syncthreads();

    float ax = 0.f, ay = 0.f, az = 0.f, aw = 0.f;
    const int doff = lane * 4;

#pragma unroll
    for (int k = 0; k < MAX_NEI; k++) {
        const size_t ia = (size_t)sA[grp][k];
        const size_t ie = (size_t)sE[grp][k];
        const float4 a = *reinterpret_cast<const float4*>(g_support + ia * D + doff);
        const float4 e = __ldcs(reinterpret_cast<const float4*>(fedges + ie * D + doff));
        ax = fmaf(a.x, e.x, ax);
        ay = fmaf(a.y, e.y, ay);
        az = fmaf(a.z, e.z, az);
        aw = fmaf(a.w, e.w, aw);
    }

    const float4 bv = *reinterpret_cast<const float4*>(bias + doff);
    float4 o;
    o.x = tanhf(ax) + bv.x;
    o.y = tanhf(ay) + bv.y;
    o.z = tanhf(az) + bv.z;
    o.w = tanhf(aw) + bv.w;
    __stcs(reinterpret_cast<float4*>(out + (size_t)node * D + doff), o);
}

// ---------------------------------------------------------------------------
// Launch
// ---------------------------------------------------------------------------
extern "C" void kernel_launch(void* const* d_in, const int* in_sizes, int n_in,
                              void* d_out, int out_size)
{
    const float* X      = (const float*)d_in[0];  // [N_NODES, D]
    const float* fedges = (const float*)d_in[1];  // [N_EDGES, D]
    const void*  a2a    = d_in[2];                // [N_NODES, 16] int64/int32
    const void*  n2e    = d_in[3];                // [N_NODES, 16] int64/int32
    const float* W      = (const float*)d_in[4];  // [D, D]
    const float* b_lin  = (const float*)d_in[5];  // [D]
    const float* bias   = (const float*)d_in[6];  // [D]
    float* out = (float*)d_out;                   // [N_NODES, D]

    const int n4x = N_NODES * D / 4;
    split_x_kernel<<<(n4x + 255) / 256, 256>>>(X, n4x);
    const int n4w = D * D / 4;
    split_w_kernel<<<(n4w + 255) / 256, 256>>>(W, n4w);

    dim3 gg((N_NODES + BM - 1) / BM, D / BN);   // (391, 2)
    gemm_mma_kernel<<<gg, 256>>>(b_lin, N_NODES);

    gather_kernel<<<N_NODES / 4, 256>>>(a2a, n2e, fedges, bias, out);
}